// round 2
// baseline (speedup 1.0000x reference)
#include <cuda_runtime.h>

#define B 8
#define CIN 16
#define COUT 32
#define EDGES 120000
#define NTOT (B * EDGES)            // 960000, divisible by 256
#define BN_EPS 1e-5f

// Scratch: transposed x [B*E, CIN] (61.4 MB) + BN stat accumulators.
__device__ float g_xT[(size_t)NTOT * CIN];
__device__ float g_sum[COUT];
__device__ float g_sumsq[COUT];
__device__ float g_scale[COUT];
__device__ float g_shift[COUT];

// ---------------------------------------------------------------------------
// Kernel 1: transpose x [B, CIN, E] -> g_xT [B*E, CIN]; zero stat buffers.
// Reads coalesced along E per channel; each thread writes its own contiguous
// 64B row (a warp covers a contiguous 2KB span) -> fully coalesced.
// ---------------------------------------------------------------------------
__global__ __launch_bounds__(256) void transpose_kernel(const float* __restrict__ x) {
    int i = blockIdx.x * 256 + threadIdx.x;
    if (blockIdx.x == 0 && threadIdx.x < 2 * COUT) {
        if (threadIdx.x < COUT) g_sum[threadIdx.x] = 0.f;
        else                    g_sumsq[threadIdx.x - COUT] = 0.f;
    }
    if (i >= NTOT) return;
    int b = i / EDGES;
    int e = i - b * EDGES;
    const float* xb = x + (size_t)b * CIN * EDGES + e;
    float v[CIN];
#pragma unroll
    for (int c = 0; c < CIN; c++) v[c] = xb[(size_t)c * EDGES];
    float4* dst = (float4*)&g_xT[(size_t)i * CIN];
#pragma unroll
    for (int q = 0; q < 4; q++)
        dst[q] = make_float4(v[4 * q], v[4 * q + 1], v[4 * q + 2], v[4 * q + 3]);
}

// ---------------------------------------------------------------------------
// Kernel 2: mesh conv + bias -> d_out. One thread per (b, e).
// W in smem laid out [cs=80][o=32] so the inner o-loop is broadcast LDS.128.
// No stats here (kept pure compute; stats done by a cheap re-read kernel).
// ---------------------------------------------------------------------------
__global__ __launch_bounds__(256) void conv_kernel(const int* __restrict__ gemm,
                                                   const float* __restrict__ W,
                                                   const float* __restrict__ bias,
                                                   float* __restrict__ out) {
    __shared__ float s_W[CIN * 5 * COUT];   // [c*5+s][o]
    __shared__ float s_bias[COUT];

    int tid = threadIdx.x;
    for (int j = tid; j < CIN * 5 * COUT; j += 256) {
        int cs = j >> 5;
        int o  = j & 31;
        s_W[j] = W[o * (CIN * 5) + cs];
    }
    if (tid < COUT) s_bias[tid] = bias[tid];
    __syncthreads();

    int i = blockIdx.x * 256 + tid;          // grid sized exactly to NTOT
    int b = i / EDGES;
    int e = i - b * EDGES;

    int4 g = ((const int4*)gemm)[i];
    size_t nb_base = (size_t)b * EDGES;
    const float4* xo = (const float4*)&g_xT[(size_t)i * CIN];
    const float4* pa = (const float4*)&g_xT[(nb_base + (size_t)g.x) * CIN];
    const float4* pb = (const float4*)&g_xT[(nb_base + (size_t)g.y) * CIN];
    const float4* pc = (const float4*)&g_xT[(nb_base + (size_t)g.z) * CIN];
    const float4* pd = (const float4*)&g_xT[(nb_base + (size_t)g.w) * CIN];

    float acc[COUT];
#pragma unroll
    for (int o = 0; o < COUT; o++) acc[o] = 0.f;

#pragma unroll
    for (int cc = 0; cc < 4; cc++) {
        float4 vx = xo[cc];
        float4 va = pa[cc];
        float4 vb = pb[cc];
        float4 vc = pc[cc];
        float4 vd = pd[cc];
        float fx[4] = {vx.x, vx.y, vx.z, vx.w};
        float fa[4] = {va.x, va.y, va.z, va.w};
        float fb[4] = {vb.x, vb.y, vb.z, vb.w};
        float fc[4] = {vc.x, vc.y, vc.z, vc.w};
        float fd[4] = {vd.x, vd.y, vd.z, vd.w};
#pragma unroll
        for (int j = 0; j < 4; j++) {
            int c = cc * 4 + j;
            float fv[5];
            fv[0] = fx[j];
            fv[1] = fabsf(fa[j] - fc[j]);
            fv[2] = fa[j] + fc[j];
            fv[3] = fabsf(fb[j] - fd[j]);
            fv[4] = fb[j] + fd[j];
#pragma unroll
            for (int s = 0; s < 5; s++) {
                const float* wr = &s_W[(c * 5 + s) * COUT];
                float f = fv[s];
#pragma unroll
                for (int o = 0; o < COUT; o++) acc[o] += f * wr[o];
            }
        }
    }

    size_t outbase = (size_t)b * COUT * EDGES + e;
#pragma unroll
    for (int o = 0; o < COUT; o++)
        out[outbase + (size_t)o * EDGES] = acc[o] + s_bias[o];
}

// ---------------------------------------------------------------------------
// Kernel 3: BN statistics. One block per (b, o) row (256 blocks total).
// Coalesced float4 reads, thread-local accumulation, one smem reduction,
// one global atomic pair per block.
// ---------------------------------------------------------------------------
__global__ __launch_bounds__(256) void stats_kernel(const float* __restrict__ out) {
    __shared__ float s1[256];
    __shared__ float s2[256];
    int blk = blockIdx.x;                 // blk = b * COUT + o
    int o   = blk & (COUT - 1);
    const float4* row = (const float4*)(out + (size_t)blk * EDGES);
    const int E4 = EDGES / 4;             // 30000

    float a1 = 0.f, a2 = 0.f;
    for (int j = threadIdx.x; j < E4; j += 256) {
        float4 v = row[j];
        a1 += v.x + v.y + v.z + v.w;
        a2 += v.x * v.x + v.y * v.y + v.z * v.z + v.w * v.w;
    }
    s1[threadIdx.x] = a1;
    s2[threadIdx.x] = a2;
    __syncthreads();
#pragma unroll
    for (int st = 128; st > 0; st >>= 1) {
        if (threadIdx.x < st) {
            s1[threadIdx.x] += s1[threadIdx.x + st];
            s2[threadIdx.x] += s2[threadIdx.x + st];
        }
        __syncthreads();
    }
    if (threadIdx.x == 0) {
        atomicAdd(&g_sum[o],   s1[0]);
        atomicAdd(&g_sumsq[o], s2[0]);
    }
}

// ---------------------------------------------------------------------------
// Kernel 4: fold BN stats + gamma/beta into per-channel scale/shift.
// ---------------------------------------------------------------------------
__global__ void finalize_kernel(const float* __restrict__ gamma,
                                const float* __restrict__ beta) {
    int o = threadIdx.x;
    if (o < COUT) {
        float inv  = 1.0f / (float)NTOT;
        float mean = g_sum[o] * inv;
        float var  = g_sumsq[o] * inv - mean * mean;
        float rstd = rsqrtf(var + BN_EPS);
        float sc   = gamma[o] * rstd;
        g_scale[o] = sc;
        g_shift[o] = beta[o] - mean * sc;
    }
}

// ---------------------------------------------------------------------------
// Kernel 5: y -> relu(y*scale + shift), in place, float4.
// ---------------------------------------------------------------------------
__global__ __launch_bounds__(256) void norm_relu_kernel(float* __restrict__ out) {
    int i = blockIdx.x * 256 + threadIdx.x;      // float4 index, exact grid
    const int E4 = EDGES / 4;
    int o = (i / E4) & (COUT - 1);
    float sc = g_scale[o];
    float sh = g_shift[o];
    float4 v = ((float4*)out)[i];
    v.x = fmaxf(fmaf(v.x, sc, sh), 0.f);
    v.y = fmaxf(fmaf(v.y, sc, sh), 0.f);
    v.z = fmaxf(fmaf(v.z, sc, sh), 0.f);
    v.w = fmaxf(fmaf(v.w, sc, sh), 0.f);
    ((float4*)out)[i] = v;
}

// ---------------------------------------------------------------------------
extern "C" void kernel_launch(void* const* d_in, const int* in_sizes, int n_in,
                              void* d_out, int out_size) {
    const float* x     = (const float*)d_in[0];
    const int*   gemm  = (const int*)  d_in[1];
    const float* W     = (const float*)d_in[2];
    const float* bias  = (const float*)d_in[3];
    const float* gamma = (const float*)d_in[4];
    const float* beta  = (const float*)d_in[5];
    float* out = (float*)d_out;

    transpose_kernel<<<NTOT / 256, 256>>>(x);
    conv_kernel<<<NTOT / 256, 256>>>(gemm, W, bias, out);
    stats_kernel<<<B * COUT, 256>>>(out);
    finalize_kernel<<<1, 32>>>(gamma, beta);
    norm_relu_kernel<<<(NTOT * COUT / 4) / 256, 256>>>(out);
}

// round 4
// speedup vs baseline: 1.0311x; 1.0311x over previous
#include <cuda_runtime.h>

#define B 8
#define CIN 16
#define COUT 32
#define EDGES 120000
#define NTOT (B * EDGES)            // 960000, divisible by 256
#define BN_EPS 1e-5f

typedef unsigned long long u64;

// Scratch: transposed x [B*E, CIN] (61.4 MB) + BN stat accumulators.
__device__ float g_xT[(size_t)NTOT * CIN];
__device__ float g_sum[COUT];
__device__ float g_sumsq[COUT];
__device__ float g_scale[COUT];
__device__ float g_shift[COUT];

// ---- packed f32x2 helpers (sm_100+) ---------------------------------------
__device__ __forceinline__ u64 splat2(float f) {
    u64 r;
    asm("mov.b64 %0, {%1, %1};" : "=l"(r) : "f"(f));
    return r;
}
__device__ __forceinline__ void ffma2(u64& acc, u64 a, u64 b) {
    asm("fma.rn.f32x2 %0, %1, %2, %0;" : "+l"(acc) : "l"(a), "l"(b));
}
__device__ __forceinline__ void unpack2(u64 v, float& lo, float& hi) {
    asm("mov.b64 {%0, %1}, %2;" : "=f"(lo), "=f"(hi) : "l"(v));
}

// ---------------------------------------------------------------------------
// Kernel 1: transpose x [B, CIN, E] -> g_xT [B*E, CIN]; zero stat buffers.
// ---------------------------------------------------------------------------
__global__ __launch_bounds__(256) void transpose_kernel(const float* __restrict__ x) {
    int i = blockIdx.x * 256 + threadIdx.x;
    if (blockIdx.x == 0 && threadIdx.x < 2 * COUT) {
        if (threadIdx.x < COUT) g_sum[threadIdx.x] = 0.f;
        else                    g_sumsq[threadIdx.x - COUT] = 0.f;
    }
    if (i >= NTOT) return;
    int b = i / EDGES;
    int e = i - b * EDGES;
    const float* xb = x + (size_t)b * CIN * EDGES + e;
    float v[CIN];
#pragma unroll
    for (int c = 0; c < CIN; c++) v[c] = xb[(size_t)c * EDGES];
    float4* dst = (float4*)&g_xT[(size_t)i * CIN];
#pragma unroll
    for (int q = 0; q < 4; q++)
        dst[q] = make_float4(v[4 * q], v[4 * q + 1], v[4 * q + 2], v[4 * q + 3]);
}

// ---------------------------------------------------------------------------
// Kernel 2: mesh conv + bias -> d_out. One thread per (b, e).
// Channel-packed f32x2: acc pair p = (ch 2p, ch 2p+1). Weights in smem
// [cs=80][o=32]; one LDS.128 yields two packed weight operands. Per-edge
// feature splatted once and reused across all 32 channels.
// ---------------------------------------------------------------------------
__global__ __launch_bounds__(256) void conv_kernel(const int* __restrict__ gemm,
                                                   const float* __restrict__ W,
                                                   const float* __restrict__ bias,
                                                   float* __restrict__ out) {
    __shared__ __align__(16) float s_W[CIN * 5 * COUT];   // [c*5+s][o]
    __shared__ __align__(16) float s_bias[COUT];

    int tid = threadIdx.x;
    for (int j = tid; j < CIN * 5 * COUT; j += 256) {
        int cs = j >> 5;
        int o  = j & 31;
        s_W[j] = W[o * (CIN * 5) + cs];
    }
    if (tid < COUT) s_bias[tid] = bias[tid];
    __syncthreads();

    int i = blockIdx.x * 256 + tid;          // grid sized exactly to NTOT
    int b = i / EDGES;
    int e = i - b * EDGES;

    int4 g = ((const int4*)gemm)[i];
    size_t nb_base = (size_t)b * EDGES;
    const float4* xo = (const float4*)&g_xT[(size_t)i * CIN];
    const float4* pa = (const float4*)&g_xT[(nb_base + (size_t)g.x) * CIN];
    const float4* pb = (const float4*)&g_xT[(nb_base + (size_t)g.y) * CIN];
    const float4* pc = (const float4*)&g_xT[(nb_base + (size_t)g.z) * CIN];
    const float4* pd = (const float4*)&g_xT[(nb_base + (size_t)g.w) * CIN];

    // acc pairs initialized with bias (folds bias add into the MAC chain)
    u64 acc[COUT / 2];
    const u64* bias2 = (const u64*)s_bias;
#pragma unroll
    for (int p = 0; p < COUT / 2; p++) acc[p] = bias2[p];

#pragma unroll
    for (int cc = 0; cc < 4; cc++) {
        float4 vx = xo[cc];
        float4 va = pa[cc];
        float4 vb = pb[cc];
        float4 vc = pc[cc];
        float4 vd = pd[cc];
        float fx[4] = {vx.x, vx.y, vx.z, vx.w};
        float fa[4] = {va.x, va.y, va.z, va.w};
        float fb[4] = {vb.x, vb.y, vb.z, vb.w};
        float fc[4] = {vc.x, vc.y, vc.z, vc.w};
        float fd[4] = {vd.x, vd.y, vd.z, vd.w};
#pragma unroll
        for (int j = 0; j < 4; j++) {
            int c = cc * 4 + j;
            float fv[5];
            fv[0] = fx[j];
            fv[1] = fabsf(fa[j] - fc[j]);
            fv[2] = fa[j] + fc[j];
            fv[3] = fabsf(fb[j] - fd[j]);
            fv[4] = fb[j] + fd[j];
#pragma unroll
            for (int s = 0; s < 5; s++) {
                u64 f2 = splat2(fv[s]);
                const ulonglong2* wr = (const ulonglong2*)&s_W[(c * 5 + s) * COUT];
#pragma unroll
                for (int q = 0; q < 8; q++) {       // 8 LDS.128 -> 16 FFMA2
                    ulonglong2 w2 = wr[q];
                    ffma2(acc[2 * q],     f2, w2.x);
                    ffma2(acc[2 * q + 1], f2, w2.y);
                }
            }
        }
    }

    size_t outbase = (size_t)b * COUT * EDGES + e;
#pragma unroll
    for (int p = 0; p < COUT / 2; p++) {
        float lo, hi;
        unpack2(acc[p], lo, hi);
        out[outbase + (size_t)(2 * p)     * EDGES] = lo;
        out[outbase + (size_t)(2 * p + 1) * EDGES] = hi;
    }
}

// ---------------------------------------------------------------------------
// Kernel 3: BN statistics. One block per (b, o) row (256 blocks total).
// ---------------------------------------------------------------------------
__global__ __launch_bounds__(256) void stats_kernel(const float* __restrict__ out) {
    __shared__ float s1[256];
    __shared__ float s2[256];
    int blk = blockIdx.x;                 // blk = b * COUT + o
    int o   = blk & (COUT - 1);
    const float4* row = (const float4*)(out + (size_t)blk * EDGES);
    const int E4 = EDGES / 4;             // 30000

    float a1 = 0.f, a2 = 0.f;
    for (int j = threadIdx.x; j < E4; j += 256) {
        float4 v = row[j];
        a1 += v.x + v.y + v.z + v.w;
        a2 += v.x * v.x + v.y * v.y + v.z * v.z + v.w * v.w;
    }
    s1[threadIdx.x] = a1;
    s2[threadIdx.x] = a2;
    __syncthreads();
#pragma unroll
    for (int st = 128; st > 0; st >>= 1) {
        if (threadIdx.x < st) {
            s1[threadIdx.x] += s1[threadIdx.x + st];
            s2[threadIdx.x] += s2[threadIdx.x + st];
        }
        __syncthreads();
    }
    if (threadIdx.x == 0) {
        atomicAdd(&g_sum[o],   s1[0]);
        atomicAdd(&g_sumsq[o], s2[0]);
    }
}

// ---------------------------------------------------------------------------
// Kernel 4: fold BN stats + gamma/beta into per-channel scale/shift.
// ---------------------------------------------------------------------------
__global__ void finalize_kernel(const float* __restrict__ gamma,
                                const float* __restrict__ beta) {
    int o = threadIdx.x;
    if (o < COUT) {
        float inv  = 1.0f / (float)NTOT;
        float mean = g_sum[o] * inv;
        float var  = g_sumsq[o] * inv - mean * mean;
        float rstd = rsqrtf(var + BN_EPS);
        float sc   = gamma[o] * rstd;
        g_scale[o] = sc;
        g_shift[o] = beta[o] - mean * sc;
    }
}

// ---------------------------------------------------------------------------
// Kernel 5: y -> relu(y*scale + shift), in place, float4.
// ---------------------------------------------------------------------------
__global__ __launch_bounds__(256) void norm_relu_kernel(float* __restrict__ out) {
    int i = blockIdx.x * 256 + threadIdx.x;      // float4 index, exact grid
    const int E4 = EDGES / 4;
    int o = (i / E4) & (COUT - 1);
    float sc = g_scale[o];
    float sh = g_shift[o];
    float4 v = ((float4*)out)[i];
    v.x = fmaxf(fmaf(v.x, sc, sh), 0.f);
    v.y = fmaxf(fmaf(v.y, sc, sh), 0.f);
    v.z = fmaxf(fmaf(v.z, sc, sh), 0.f);
    v.w = fmaxf(fmaf(v.w, sc, sh), 0.f);
    ((float4*)out)[i] = v;
}

// ---------------------------------------------------------------------------
extern "C" void kernel_launch(void* const* d_in, const int* in_sizes, int n_in,
                              void* d_out, int out_size) {
    const float* x     = (const float*)d_in[0];
    const int*   gemm  = (const int*)  d_in[1];
    const float* W     = (const float*)d_in[2];
    const float* bias  = (const float*)d_in[3];
    const float* gamma = (const float*)d_in[4];
    const float* beta  = (const float*)d_in[5];
    float* out = (float*)d_out;

    transpose_kernel<<<NTOT / 256, 256>>>(x);
    conv_kernel<<<NTOT / 256, 256>>>(gemm, W, bias, out);
    stats_kernel<<<B * COUT, 256>>>(out);
    finalize_kernel<<<1, 32>>>(gamma, beta);
    norm_relu_kernel<<<(NTOT * COUT / 4) / 256, 256>>>(out);
}

// round 7
// speedup vs baseline: 1.3055x; 1.2662x over previous
#include <cuda_runtime.h>

#define B 8
#define CIN 16
#define COUT 32
#define EDGES 120000
#define NTOT (B * EDGES)            // 960000
#define BN_EPS 1e-5f

typedef unsigned long long u64;

// Scratch: transposed x [B*E, CIN] (61.4 MB) + BN stat accumulators.
__device__ float g_xT[(size_t)NTOT * CIN];
__device__ float g_sum[COUT];
__device__ float g_sumsq[COUT];

// ---- packed f32x2 helpers (sm_100+) ---------------------------------------
__device__ __forceinline__ u64 splat2(float f) {
    u64 r;
    asm("mov.b64 %0, {%1, %1};" : "=l"(r) : "f"(f));
    return r;
}
__device__ __forceinline__ void ffma2(u64& acc, u64 a, u64 b) {
    asm("fma.rn.f32x2 %0, %1, %2, %0;" : "+l"(acc) : "l"(a), "l"(b));
}
__device__ __forceinline__ void unpack2(u64 v, float& lo, float& hi) {
    asm("mov.b64 {%0, %1}, %2;" : "=f"(lo), "=f"(hi) : "l"(v));
}

// ---------------------------------------------------------------------------
// Kernel 1: transpose x [B, CIN, E] -> g_xT [B*E, CIN]; zero stat buffers.
// ---------------------------------------------------------------------------
__global__ __launch_bounds__(256) void transpose_kernel(const float* __restrict__ x) {
    int i = blockIdx.x * 256 + threadIdx.x;
    if (blockIdx.x == 0 && threadIdx.x < 2 * COUT) {
        if (threadIdx.x < COUT) g_sum[threadIdx.x] = 0.f;
        else                    g_sumsq[threadIdx.x - COUT] = 0.f;
    }
    if (i >= NTOT) return;
    int b = i / EDGES;
    int e = i - b * EDGES;
    const float* xb = x + (size_t)b * CIN * EDGES + e;
    float v[CIN];
#pragma unroll
    for (int c = 0; c < CIN; c++) v[c] = xb[(size_t)c * EDGES];
    float4* dst = (float4*)&g_xT[(size_t)i * CIN];
#pragma unroll
    for (int q = 0; q < 4; q++)
        dst[q] = make_float4(v[4 * q], v[4 * q + 1], v[4 * q + 2], v[4 * q + 3]);
}

// ---------------------------------------------------------------------------
// Kernel 2: mesh conv + bias -> d_out. TWO consecutive edges per thread.
// Channel-packed f32x2 accumulators (pair p = ch 2p, 2p+1) for each edge;
// one set of smem weight loads (LDS.128) feeds BOTH edges. 10 gather rows
// in flight per thread for deep MLP against L2 latency.
// ---------------------------------------------------------------------------
__global__ __launch_bounds__(128, 3) void conv_kernel(const int* __restrict__ gemm,
                                                      const float* __restrict__ W,
                                                      const float* __restrict__ bias,
                                                      float* __restrict__ out) {
    __shared__ __align__(16) float s_W[CIN * 5 * COUT];   // [c*5+s][o]
    __shared__ __align__(16) float s_bias[COUT];

    int tid = threadIdx.x;
    for (int j = tid; j < CIN * 5 * COUT; j += 128) {
        int cs = j >> 5;
        int o  = j & 31;
        s_W[j] = W[o * (CIN * 5) + cs];
    }
    if (tid < COUT) s_bias[tid] = bias[tid];
    __syncthreads();

    int t  = blockIdx.x * 128 + tid;         // pair index, grid exact
    int i0 = 2 * t;                          // first edge (even)
    int b  = i0 / EDGES;                     // EDGES even -> pair in one batch
    int e  = i0 - b * EDGES;

    int4 g0 = ((const int4*)gemm)[i0];
    int4 g1 = ((const int4*)gemm)[i0 + 1];
    size_t nb = (size_t)b * EDGES;
    const float4* x0 = (const float4*)&g_xT[(size_t)i0 * CIN];
    const float4* x1 = (const float4*)&g_xT[(size_t)(i0 + 1) * CIN];
    const float4* a0 = (const float4*)&g_xT[(nb + (size_t)g0.x) * CIN];
    const float4* b0 = (const float4*)&g_xT[(nb + (size_t)g0.y) * CIN];
    const float4* c0 = (const float4*)&g_xT[(nb + (size_t)g0.z) * CIN];
    const float4* d0 = (const float4*)&g_xT[(nb + (size_t)g0.w) * CIN];
    const float4* a1 = (const float4*)&g_xT[(nb + (size_t)g1.x) * CIN];
    const float4* b1 = (const float4*)&g_xT[(nb + (size_t)g1.y) * CIN];
    const float4* c1 = (const float4*)&g_xT[(nb + (size_t)g1.z) * CIN];
    const float4* d1 = (const float4*)&g_xT[(nb + (size_t)g1.w) * CIN];

    u64 acc0[COUT / 2], acc1[COUT / 2];
    const u64* bias2 = (const u64*)s_bias;
#pragma unroll
    for (int p = 0; p < COUT / 2; p++) { acc0[p] = bias2[p]; acc1[p] = bias2[p]; }

#pragma unroll
    for (int cc = 0; cc < 4; cc++) {
        float4 vx0 = x0[cc], va0 = a0[cc], vb0 = b0[cc], vc0 = c0[cc], vd0 = d0[cc];
        float4 vx1 = x1[cc], va1 = a1[cc], vb1 = b1[cc], vc1 = c1[cc], vd1 = d1[cc];
        float fx0[4] = {vx0.x, vx0.y, vx0.z, vx0.w};
        float fa0[4] = {va0.x, va0.y, va0.z, va0.w};
        float fb0[4] = {vb0.x, vb0.y, vb0.z, vb0.w};
        float fc0[4] = {vc0.x, vc0.y, vc0.z, vc0.w};
        float fd0[4] = {vd0.x, vd0.y, vd0.z, vd0.w};
        float fx1[4] = {vx1.x, vx1.y, vx1.z, vx1.w};
        float fa1[4] = {va1.x, va1.y, va1.z, va1.w};
        float fb1[4] = {vb1.x, vb1.y, vb1.z, vb1.w};
        float fc1[4] = {vc1.x, vc1.y, vc1.z, vc1.w};
        float fd1[4] = {vd1.x, vd1.y, vd1.z, vd1.w};
#pragma unroll
        for (int j = 0; j < 4; j++) {
            int c = cc * 4 + j;
            float fv0[5], fv1[5];
            fv0[0] = fx0[j];
            fv0[1] = fabsf(fa0[j] - fc0[j]);
            fv0[2] = fa0[j] + fc0[j];
            fv0[3] = fabsf(fb0[j] - fd0[j]);
            fv0[4] = fb0[j] + fd0[j];
            fv1[0] = fx1[j];
            fv1[1] = fabsf(fa1[j] - fc1[j]);
            fv1[2] = fa1[j] + fc1[j];
            fv1[3] = fabsf(fb1[j] - fd1[j]);
            fv1[4] = fb1[j] + fd1[j];
#pragma unroll
            for (int s = 0; s < 5; s++) {
                u64 f20 = splat2(fv0[s]);
                u64 f21 = splat2(fv1[s]);
                const ulonglong2* wr = (const ulonglong2*)&s_W[(c * 5 + s) * COUT];
#pragma unroll
                for (int q = 0; q < 8; q++) {   // 8 LDS.128 feed BOTH edges
                    ulonglong2 w2 = wr[q];
                    ffma2(acc0[2 * q],     f20, w2.x);
                    ffma2(acc0[2 * q + 1], f20, w2.y);
                    ffma2(acc1[2 * q],     f21, w2.x);
                    ffma2(acc1[2 * q + 1], f21, w2.y);
                }
            }
        }
    }

    // e even: float2 store covers edges e, e+1 for each channel.
    float* ob = out + (size_t)b * COUT * EDGES + e;
#pragma unroll
    for (int p = 0; p < COUT / 2; p++) {
        float l0, h0, l1, h1;
        unpack2(acc0[p], l0, h0);
        unpack2(acc1[p], l1, h1);
        *(float2*)(ob + (size_t)(2 * p)     * EDGES) = make_float2(l0, l1);
        *(float2*)(ob + (size_t)(2 * p + 1) * EDGES) = make_float2(h0, h1);
    }
}

// ---------------------------------------------------------------------------
// Kernel 3: BN statistics. 4 chunk-blocks per (b, o) row (1024 blocks).
// ---------------------------------------------------------------------------
__global__ __launch_bounds__(256) void stats_kernel(const float* __restrict__ out) {
    __shared__ float s1[256];
    __shared__ float s2[256];
    int blk   = blockIdx.x;               // blk = (b*COUT + o) * 4 + chunk
    int row   = blk >> 2;
    int chunk = blk & 3;
    int o     = row & (COUT - 1);
    const int E4 = EDGES / 4;             // 30000 float4 per row
    const int C4 = E4 / 4;                // 7500 float4 per chunk
    const float4* rp = (const float4*)(out + (size_t)row * EDGES) + chunk * C4;

    float a1 = 0.f, a2 = 0.f;
    for (int j = threadIdx.x; j < C4; j += 256) {
        float4 v = rp[j];
        a1 += v.x + v.y + v.z + v.w;
        a2 += v.x * v.x + v.y * v.y + v.z * v.z + v.w * v.w;
    }
    s1[threadIdx.x] = a1;
    s2[threadIdx.x] = a2;
    __syncthreads();
#pragma unroll
    for (int st = 128; st > 0; st >>= 1) {
        if (threadIdx.x < st) {
            s1[threadIdx.x] += s1[threadIdx.x + st];
            s2[threadIdx.x] += s2[threadIdx.x + st];
        }
        __syncthreads();
    }
    if (threadIdx.x == 0) {
        atomicAdd(&g_sum[o],   s1[0]);
        atomicAdd(&g_sumsq[o], s2[0]);
    }
}

// ---------------------------------------------------------------------------
// Kernel 4: y -> relu(y*scale + shift), in place. Scale/shift computed from
// the global stat accumulators in-block (finalize merged; one less launch).
// ---------------------------------------------------------------------------
__global__ __launch_bounds__(256) void norm_relu_kernel(float* __restrict__ out,
                                                        const float* __restrict__ gamma,
                                                        const float* __restrict__ beta) {
    __shared__ float s_scale[COUT];
    __shared__ float s_shift[COUT];
    if (threadIdx.x < COUT) {
        int o = threadIdx.x;
        float inv  = 1.0f / (float)NTOT;
        float mean = g_sum[o] * inv;
        float var  = g_sumsq[o] * inv - mean * mean;
        float rstd = rsqrtf(var + BN_EPS);
        float sc   = gamma[o] * rstd;
        s_scale[o] = sc;
        s_shift[o] = beta[o] - mean * sc;
    }
    __syncthreads();

    int i = blockIdx.x * 256 + threadIdx.x;      // float4 index, exact grid
    const int E4 = EDGES / 4;
    int o = (i / E4) & (COUT - 1);
    float sc = s_scale[o];
    float sh = s_shift[o];
    float4 v = ((float4*)out)[i];
    v.x = fmaxf(fmaf(v.x, sc, sh), 0.f);
    v.y = fmaxf(fmaf(v.y, sc, sh), 0.f);
    v.z = fmaxf(fmaf(v.z, sc, sh), 0.f);
    v.w = fmaxf(fmaf(v.w, sc, sh), 0.f);
    ((float4*)out)[i] = v;
}

// ---------------------------------------------------------------------------
extern "C" void kernel_launch(void* const* d_in, const int* in_sizes, int n_in,
                              void* d_out, int out_size) {
    const float* x     = (const float*)d_in[0];
    const int*   gemm  = (const int*)  d_in[1];
    const float* W     = (const float*)d_in[2];
    const float* bias  = (const float*)d_in[3];
    const float* gamma = (const float*)d_in[4];
    const float* beta  = (const float*)d_in[5];
    float* out = (float*)d_out;

    transpose_kernel<<<NTOT / 256, 256>>>(x);
    conv_kernel<<<NTOT / 2 / 128, 128>>>(gemm, W, bias, out);
    stats_kernel<<<B * COUT * 4, 256>>>(out);
    norm_relu_kernel<<<(NTOT * COUT / 4) / 256, 256>>>(out, gamma, beta);
}

// round 8
// speedup vs baseline: 1.4103x; 1.0803x over previous
#include <cuda_runtime.h>

#define B 8
#define CIN 16
#define COUT 32
#define EDGES 120000
#define NTOT (B * EDGES)            // 960000
#define BN_EPS 1e-5f

typedef unsigned long long u64;

// Scratch: transposed x [B*E, CIN] (61.4 MB) + BN stat accumulators.
__device__ float g_xT[(size_t)NTOT * CIN];
__device__ float g_sum[COUT];
__device__ float g_sumsq[COUT];

// ---- packed f32x2 helpers (sm_100+) ---------------------------------------
__device__ __forceinline__ u64 splat2(float f) {
    u64 r;
    asm("mov.b64 %0, {%1, %1};" : "=l"(r) : "f"(f));
    return r;
}
__device__ __forceinline__ void ffma2(u64& acc, u64 a, u64 b) {
    asm("fma.rn.f32x2 %0, %1, %2, %0;" : "+l"(acc) : "l"(a), "l"(b));
}
__device__ __forceinline__ void unpack2(u64 v, float& lo, float& hi) {
    asm("mov.b64 {%0, %1}, %2;" : "=f"(lo), "=f"(hi) : "l"(v));
}

// ---------------------------------------------------------------------------
// Kernel 1: transpose x [B, CIN, E] -> g_xT [B*E, CIN]; zero stat buffers.
// ---------------------------------------------------------------------------
__global__ __launch_bounds__(256) void transpose_kernel(const float* __restrict__ x) {
    int i = blockIdx.x * 256 + threadIdx.x;
    if (blockIdx.x == 0 && threadIdx.x < 2 * COUT) {
        if (threadIdx.x < COUT) g_sum[threadIdx.x] = 0.f;
        else                    g_sumsq[threadIdx.x - COUT] = 0.f;
    }
    if (i >= NTOT) return;
    int b = i / EDGES;
    int e = i - b * EDGES;
    const float* xb = x + (size_t)b * CIN * EDGES + e;
    float v[CIN];
#pragma unroll
    for (int c = 0; c < CIN; c++) v[c] = xb[(size_t)c * EDGES];
    float4* dst = (float4*)&g_xT[(size_t)i * CIN];
#pragma unroll
    for (int q = 0; q < 4; q++)
        dst[q] = make_float4(v[4 * q], v[4 * q + 1], v[4 * q + 2], v[4 * q + 3]);
}

// ---------------------------------------------------------------------------
// Kernel 2: mesh conv + bias -> d_out. FOUR consecutive edges per thread.
// Channel-packed f32x2 accumulators (pair p = ch 2p, 2p+1) per edge; one set
// of smem weight LDS.128 feeds all four edges (per-edge crossbar cost /4 vs
// 1-edge). 20 gather rows in flight per thread. Output: STG.128 per channel.
// ---------------------------------------------------------------------------
__global__ __launch_bounds__(128, 2) void conv_kernel(const int* __restrict__ gemm,
                                                      const float* __restrict__ W,
                                                      const float* __restrict__ bias,
                                                      float* __restrict__ out) {
    __shared__ __align__(16) float s_W[CIN * 5 * COUT];   // [c*5+s][o]
    __shared__ __align__(16) float s_bias[COUT];

    int tid = threadIdx.x;
    for (int j = tid; j < CIN * 5 * COUT; j += 128) {
        int cs = j >> 5;
        int o  = j & 31;
        s_W[j] = W[o * (CIN * 5) + cs];
    }
    if (tid < COUT) s_bias[tid] = bias[tid];
    __syncthreads();

    int t  = blockIdx.x * 128 + tid;         // quad index, grid exact
    int i0 = 4 * t;                          // first edge (multiple of 4)
    int b  = i0 / EDGES;                     // EDGES % 4 == 0 -> quad in one batch
    int e  = i0 - b * EDGES;
    size_t nb = (size_t)b * EDGES;

    int4 g[4];
#pragma unroll
    for (int k = 0; k < 4; k++) g[k] = ((const int4*)gemm)[i0 + k];

    const float4* px[4];
    const float4* pa[4];
    const float4* pb[4];
    const float4* pc[4];
    const float4* pd[4];
#pragma unroll
    for (int k = 0; k < 4; k++) {
        px[k] = (const float4*)&g_xT[(size_t)(i0 + k) * CIN];
        pa[k] = (const float4*)&g_xT[(nb + (size_t)g[k].x) * CIN];
        pb[k] = (const float4*)&g_xT[(nb + (size_t)g[k].y) * CIN];
        pc[k] = (const float4*)&g_xT[(nb + (size_t)g[k].z) * CIN];
        pd[k] = (const float4*)&g_xT[(nb + (size_t)g[k].w) * CIN];
    }

    // acc[k][p]: edge k, channel pair p (ch 2p, 2p+1), bias-initialized.
    u64 acc[4][COUT / 2];
    const u64* bias2 = (const u64*)s_bias;
#pragma unroll
    for (int k = 0; k < 4; k++)
#pragma unroll
        for (int p = 0; p < COUT / 2; p++) acc[k][p] = bias2[p];

#pragma unroll
    for (int cc = 0; cc < 4; cc++) {
        float4 vx[4], va[4], vb[4], vc[4], vd[4];
#pragma unroll
        for (int k = 0; k < 4; k++) {
            vx[k] = px[k][cc];
            va[k] = pa[k][cc];
            vb[k] = pb[k][cc];
            vc[k] = pc[k][cc];
            vd[k] = pd[k][cc];
        }
#pragma unroll
        for (int j = 0; j < 4; j++) {
            int c = cc * 4 + j;
            float fv[4][5];
#pragma unroll
            for (int k = 0; k < 4; k++) {
                float fx = (&vx[k].x)[j];
                float fa = (&va[k].x)[j];
                float fb = (&vb[k].x)[j];
                float fc = (&vc[k].x)[j];
                float fd = (&vd[k].x)[j];
                fv[k][0] = fx;
                fv[k][1] = fabsf(fa - fc);
                fv[k][2] = fa + fc;
                fv[k][3] = fabsf(fb - fd);
                fv[k][4] = fb + fd;
            }
#pragma unroll
            for (int s = 0; s < 5; s++) {
                u64 f2[4];
#pragma unroll
                for (int k = 0; k < 4; k++) f2[k] = splat2(fv[k][s]);
                const ulonglong2* wr = (const ulonglong2*)&s_W[(c * 5 + s) * COUT];
#pragma unroll
                for (int q = 0; q < 8; q++) {   // one LDS.128 feeds 4 edges
                    ulonglong2 w2 = wr[q];
#pragma unroll
                    for (int k = 0; k < 4; k++) {
                        ffma2(acc[k][2 * q],     f2[k], w2.x);
                        ffma2(acc[k][2 * q + 1], f2[k], w2.y);
                    }
                }
            }
        }
    }

    // e % 4 == 0: float4 store covers edges e..e+3 for each channel.
    float* ob = out + (size_t)b * COUT * EDGES + e;
#pragma unroll
    for (int p = 0; p < COUT / 2; p++) {
        float lo[4], hi[4];
#pragma unroll
        for (int k = 0; k < 4; k++) unpack2(acc[k][p], lo[k], hi[k]);
        *(float4*)(ob + (size_t)(2 * p)     * EDGES) = make_float4(lo[0], lo[1], lo[2], lo[3]);
        *(float4*)(ob + (size_t)(2 * p + 1) * EDGES) = make_float4(hi[0], hi[1], hi[2], hi[3]);
    }
}

// ---------------------------------------------------------------------------
// Kernel 3: BN statistics. 4 chunk-blocks per (b, o) row (1024 blocks).
// ---------------------------------------------------------------------------
__global__ __launch_bounds__(256) void stats_kernel(const float* __restrict__ out) {
    __shared__ float s1[256];
    __shared__ float s2[256];
    int blk   = blockIdx.x;               // blk = (b*COUT + o) * 4 + chunk
    int row   = blk >> 2;
    int chunk = blk & 3;
    int o     = row & (COUT - 1);
    const int E4 = EDGES / 4;             // 30000 float4 per row
    const int C4 = E4 / 4;                // 7500 float4 per chunk
    const float4* rp = (const float4*)(out + (size_t)row * EDGES) + chunk * C4;

    float a1 = 0.f, a2 = 0.f;
    for (int j = threadIdx.x; j < C4; j += 256) {
        float4 v = rp[j];
        a1 += v.x + v.y + v.z + v.w;
        a2 += v.x * v.x + v.y * v.y + v.z * v.z + v.w * v.w;
    }
    s1[threadIdx.x] = a1;
    s2[threadIdx.x] = a2;
    __syncthreads();
#pragma unroll
    for (int st = 128; st > 0; st >>= 1) {
        if (threadIdx.x < st) {
            s1[threadIdx.x] += s1[threadIdx.x + st];
            s2[threadIdx.x] += s2[threadIdx.x + st];
        }
        __syncthreads();
    }
    if (threadIdx.x == 0) {
        atomicAdd(&g_sum[o],   s1[0]);
        atomicAdd(&g_sumsq[o], s2[0]);
    }
}

// ---------------------------------------------------------------------------
// Kernel 4: y -> relu(y*scale + shift), in place. Scale/shift computed from
// the global stat accumulators in-block (finalize merged).
// ---------------------------------------------------------------------------
__global__ __launch_bounds__(256) void norm_relu_kernel(float* __restrict__ out,
                                                        const float* __restrict__ gamma,
                                                        const float* __restrict__ beta) {
    __shared__ float s_scale[COUT];
    __shared__ float s_shift[COUT];
    if (threadIdx.x < COUT) {
        int o = threadIdx.x;
        float inv  = 1.0f / (float)NTOT;
        float mean = g_sum[o] * inv;
        float var  = g_sumsq[o] * inv - mean * mean;
        float rstd = rsqrtf(var + BN_EPS);
        float sc   = gamma[o] * rstd;
        s_scale[o] = sc;
        s_shift[o] = beta[o] - mean * sc;
    }
    __syncthreads();

    int i = blockIdx.x * 256 + threadIdx.x;      // float4 index, exact grid
    const int E4 = EDGES / 4;
    int o = (i / E4) & (COUT - 1);
    float sc = s_scale[o];
    float sh = s_shift[o];
    float4 v = ((float4*)out)[i];
    v.x = fmaxf(fmaf(v.x, sc, sh), 0.f);
    v.y = fmaxf(fmaf(v.y, sc, sh), 0.f);
    v.z = fmaxf(fmaf(v.z, sc, sh), 0.f);
    v.w = fmaxf(fmaf(v.w, sc, sh), 0.f);
    ((float4*)out)[i] = v;
}

// ---------------------------------------------------------------------------
extern "C" void kernel_launch(void* const* d_in, const int* in_sizes, int n_in,
                              void* d_out, int out_size) {
    const float* x     = (const float*)d_in[0];
    const int*   gemm  = (const int*)  d_in[1];
    const float* W     = (const float*)d_in[2];
    const float* bias  = (const float*)d_in[3];
    const float* gamma = (const float*)d_in[4];
    const float* beta  = (const float*)d_in[5];
    float* out = (float*)d_out;

    transpose_kernel<<<NTOT / 256, 256>>>(x);
    conv_kernel<<<NTOT / 4 / 128, 128>>>(gemm, W, bias, out);
    stats_kernel<<<B * COUT * 4, 256>>>(out);
    norm_relu_kernel<<<(NTOT * COUT / 4) / 256, 256>>>(out, gamma, beta);
}